// round 6
// baseline (speedup 1.0000x reference)
#include <cuda_runtime.h>
#include <cuda_fp16.h>
#include <math.h>

#define N_NODES  50000
#define N_EDGES  800000
#define N_GRAPHS 64
#define SCAN_B   1024
#define NB_SCAN  ((N_NODES + SCAN_B - 1) / SCAN_B)   // 49
#define PA 40   // smem pitch in halves (conflict-free for frag loads)

// ---------------- scratch (device globals; no allocation allowed) ----------
__device__ __align__(16) __half g_h0hi[N_NODES * 256];
__device__ __align__(16) __half g_h0lo[N_NODES * 256];
__device__ __align__(16) __half g_a1hi[N_NODES * 256];
__device__ __align__(16) __half g_a1lo[N_NODES * 256];
__device__ __align__(16) __half g_h1hi[N_NODES * 256];
__device__ __align__(16) __half g_h1lo[N_NODES * 256];
__device__ __align__(16) float  g_pq[N_NODES * 256];    // cols 0-127: p=h1@Wl2, 128-255: q=h1@Wr2+b2
__device__ __align__(16) __half g_W1hi[256 * 512];      // [n][k] k-major, k<256: Wl1, k>=256: Wr1
__device__ __align__(16) __half g_W1lo[256 * 512];
__device__ __align__(16) __half g_W2hi[256 * 256];      // [n][k], n<128: Wl2, n>=128: Wr2
__device__ __align__(16) __half g_W2lo[256 * 256];
__device__ float g_dinv[N_NODES];
__device__ int   g_cnt[N_NODES];
__device__ int   g_rowstart[N_NODES];
__device__ int   g_cursor[N_NODES];
__device__ int   g_inlist[N_EDGES];
__device__ float g_gsum[N_GRAPHS * 128];
__device__ int   g_gcnt[N_GRAPHS];
__device__ int   g_bsums[64];

// dtype flags + device-side half-plane pointer table
__device__ int     g_ei64;
__device__ int     g_b64;
__device__ __half* g_hp[10];  // 0:h0hi 1:h0lo 2:a1hi 3:a1lo 4:h1hi 5:h1lo 6:W1hi 7:W1lo 8:W2hi 9:W2lo

// int64-or-int32 index accessor
__device__ __forceinline__ int ld_idx(const void* p, long long i, int is64) {
    return is64 ? (int)((const long long*)p)[i] : ((const int*)p)[i];
}

__device__ __forceinline__ void split_f32(float v, __half& hi, __half& lo) {
    hi = __float2half_rn(v);
    lo = __float2half_rn(v - __half2float(hi));
}

// ---------------- setup: dtype detect + pointers + zero + weight split ------
__global__ void k_setup(const int* ei_w, const int* b_w,
                        const float* __restrict__ Wl1, const float* __restrict__ Wr1,
                        const float* __restrict__ Wl2, const float* __restrict__ Wr2) {
    int i = blockIdx.x * blockDim.x + threadIdx.x;
    if (i == 0) {
        int a = 1;
        for (int k = 0; k < 64; k++) if (ei_w[2 * k + 1] != 0) { a = 0; break; }
        g_ei64 = a;
        a = 1;
        for (int k = 0; k < 64; k++) if (b_w[49001 + 2 * k] != 0) { a = 0; break; }
        g_b64 = a;

        g_hp[0] = g_h0hi; g_hp[1] = g_h0lo;
        g_hp[2] = g_a1hi; g_hp[3] = g_a1lo;
        g_hp[4] = g_h1hi; g_hp[5] = g_h1lo;
        g_hp[6] = g_W1hi; g_hp[7] = g_W1lo;
        g_hp[8] = g_W2hi; g_hp[9] = g_W2lo;
    }
    // weight split (i in [0, 196608))
    if (i < 131072) {                       // W1: [n=256][k=512]
        int n = i >> 9, k = i & 511;
        float w = (k < 256) ? Wl1[k * 256 + n] : Wr1[(k - 256) * 256 + n];
        split_f32(w, g_W1hi[i], g_W1lo[i]);
    } else if (i < 196608) {                // W2: [n=256][k=256]
        int j = i - 131072;
        int n = j >> 8, k = j & 255;
        float w = (n < 128) ? Wl2[k * 128 + n] : Wr2[k * 128 + (n - 128)];
        split_f32(w, g_W2hi[j], g_W2lo[j]);
    }
    // zeroing (strided)
    int stride = gridDim.x * blockDim.x;
    for (int j = i; j < N_NODES; j += stride) g_cnt[j] = 0;
    for (int j = i; j < N_GRAPHS * 128; j += stride) g_gsum[j] = 0.0f;
    for (int j = i; j < N_GRAPHS; j += stride) g_gcnt[j] = 0;
}

// ---------------- CSR build -------------------------------------------------
__global__ void k_count(const void* __restrict__ ei) {
    int is64 = g_ei64;
    int i = blockIdx.x * blockDim.x + threadIdx.x;
    int stride = gridDim.x * blockDim.x;
    for (int e = i; e < N_EDGES; e += stride) {
        int d = ld_idx(ei, (long long)N_EDGES + e, is64);
        atomicAdd(&g_cnt[d], 1);
    }
}

__global__ void k_scan1() {
    __shared__ int s[SCAN_B];
    int i = blockIdx.x * SCAN_B + threadIdx.x;
    int v = (i < N_NODES) ? g_cnt[i] : 0;
    s[threadIdx.x] = v;
    __syncthreads();
    for (int off = 1; off < SCAN_B; off <<= 1) {
        int t = (threadIdx.x >= off) ? s[threadIdx.x - off] : 0;
        __syncthreads();
        s[threadIdx.x] += t;
        __syncthreads();
    }
    if (i < N_NODES) g_rowstart[i] = s[threadIdx.x];
    if (threadIdx.x == SCAN_B - 1) g_bsums[blockIdx.x] = s[SCAN_B - 1];
}

__global__ void k_scan2() {
    int run = 0;
    for (int b = 0; b < NB_SCAN; b++) {
        int t = g_bsums[b];
        g_bsums[b] = run;
        run += t;
    }
}

__global__ void k_scan3() {
    int i = blockIdx.x * SCAN_B + threadIdx.x;
    if (i >= N_NODES) return;
    int incl = g_rowstart[i];
    int excl = incl - g_cnt[i] + g_bsums[i >> 10];
    g_rowstart[i] = excl;
    g_cursor[i] = excl;
}

__global__ void k_scatter(const void* __restrict__ ei) {
    int is64 = g_ei64;
    int i = blockIdx.x * blockDim.x + threadIdx.x;
    int stride = gridDim.x * blockDim.x;
    for (int e = i; e < N_EDGES; e += stride) {
        int s = ld_idx(ei, e, is64);
        int d = ld_idx(ei, (long long)N_EDGES + e, is64);
        int pos = atomicAdd(&g_cursor[d], 1);
        g_inlist[pos] = s;
    }
}

// ---------------- layer 0 (rank-1): warp per node ---------------------------
__global__ void k_layer0(const float* __restrict__ x,
                         const float* __restrict__ Wl0,
                         const float* __restrict__ b0,
                         const float* __restrict__ Wr0) {
    int wid = (blockIdx.x * blockDim.x + threadIdx.x) >> 5;
    int lane = threadIdx.x & 31;
    if (wid >= N_NODES) return;
    int deg = g_cnt[wid];
    int start = g_rowstart[wid];
    float s = 0.0f;
    for (int i = lane; i < deg; i += 32) s += x[g_inlist[start + i]];
    #pragma unroll
    for (int o = 16; o; o >>= 1) s += __shfl_xor_sync(0xFFFFFFFFu, s, o);
    float dinv = 1.0f / fmaxf((float)deg, 1.0f);
    if (lane == 0) g_dinv[wid] = dinv;
    float agg = s * dinv;
    float xv = x[wid];
    #pragma unroll
    for (int i = 0; i < 8; i++) {
        int f = i * 32 + lane;
        float v = fmaf(agg, Wl0[f], fmaf(xv, Wr0[f], b0[f]));
        v = fmaxf(v, 0.0f);
        __half hi, lo;
        split_f32(v, hi, lo);
        g_h0hi[wid * 256 + f] = hi;
        g_h0lo[wid * 256 + f] = lo;
    }
}

// ---------------- gather1: vectorized mean-aggregate h0 -> a1 planes --------
// Block = 128 threads = 4 warps per node. Per edge: warp loads the FULL
// 256-feature plane row as one uint4 warp-LDG (32 lanes x 8 halves).
//   warp0: hi plane, even edges    warp1: lo plane, even edges
//   warp2: hi plane, odd  edges    warp3: lo plane, odd  edges
// Partial sums (8 floats/lane) combine via smem at the end.
__global__ void __launch_bounds__(128)
k_gather1v() {
    int n = blockIdx.x;
    int deg = g_cnt[n];
    int start = g_rowstart[n];
    int tid = threadIdx.x;
    int wid = tid >> 5;
    int lane = tid & 31;
    int plane = wid & 1;      // 0 = hi, 1 = lo
    int eoff = wid >> 1;      // edge parity handled by this warp

    __shared__ int es[64];
    __shared__ float red[4][256];

    const __half* basep = plane ? g_h0lo : g_h0hi;
    float acc[8];
    #pragma unroll
    for (int q = 0; q < 8; q++) acc[q] = 0.0f;

    for (int b0 = 0; b0 < deg; b0 += 64) {
        int m = min(64, deg - b0);
        __syncthreads();
        if (tid < m) es[tid] = g_inlist[start + b0 + tid];
        __syncthreads();
        for (int e = eoff; e < m; e += 2) {
            int r = es[e];
            uint4 v = *(const uint4*)&basep[(size_t)r * 256 + lane * 8];
            const __half2* h = (const __half2*)&v;
            #pragma unroll
            for (int q = 0; q < 4; q++) {
                float2 f = __half22float2(h[q]);
                acc[2 * q]     += f.x;
                acc[2 * q + 1] += f.y;
            }
        }
    }

    #pragma unroll
    for (int q = 0; q < 8; q++) red[wid][lane * 8 + q] = acc[q];
    __syncthreads();

    if (wid == 0) {
        float dinv = g_dinv[n];
        __align__(16) __half hbuf[8], lbuf[8];
        #pragma unroll
        for (int q = 0; q < 8; q++) {
            int f = lane * 8 + q;
            float s = red[0][f] + red[1][f] + red[2][f] + red[3][f];
            split_f32(s * dinv, hbuf[q], lbuf[q]);
        }
        *(uint4*)&g_a1hi[(size_t)n * 256 + lane * 8] = *(uint4*)hbuf;
        *(uint4*)&g_a1lo[(size_t)n * 256 + lane * 8] = *(uint4*)lbuf;
    }
}

// ---------------- split-fp16 tensor-core GEMM --------------------------------
__device__ __forceinline__ void mma16816(float* d, const unsigned* a, const unsigned* b) {
    asm volatile(
        "mma.sync.aligned.m16n8k16.row.col.f32.f16.f16.f32 "
        "{%0,%1,%2,%3}, {%4,%5,%6,%7}, {%8,%9}, {%0,%1,%2,%3};\n"
        : "+f"(d[0]), "+f"(d[1]), "+f"(d[2]), "+f"(d[3])
        : "r"(a[0]), "r"(a[1]), "r"(a[2]), "r"(a[3]), "r"(b[0]), "r"(b[1]));
}

__global__ void __launch_bounds__(256, 2)
k_hgemm(int sA0, int K0, int sA1, int K1, int sB,
        const float* __restrict__ bias, int bias_from, int relu,
        int outHalf, int sOutHi, int nrows, int ncols) {
    const __half* A0h = g_hp[sA0];
    const __half* A0l = g_hp[sA0 + 1];
    const __half* A1h = (sA1 >= 0) ? g_hp[sA1] : (const __half*)0;
    const __half* A1l = (sA1 >= 0) ? g_hp[sA1 + 1] : (const __half*)0;
    const __half* Bh = g_hp[sB];
    const __half* Bl = g_hp[sB + 1];
    __half* Oh = outHalf ? g_hp[sOutHi] : (__half*)0;
    __half* Ol = outHalf ? g_hp[sOutHi + 1] : (__half*)0;

    __shared__ __half As[2][128 * PA];
    __shared__ __half Bs[2][128 * PA];

    int tid = threadIdx.x;
    int lane = tid & 31;
    int wid = tid >> 5;
    int wm = wid & 1;
    int wn = wid >> 1;
    int g = lane >> 2;
    int t2 = (lane & 3) * 2;
    int rowBase = blockIdx.y * 128;
    int colBase = blockIdx.x * 128;
    int K = K0 + K1;

    float c[4][4][4];
    #pragma unroll
    for (int i = 0; i < 4; i++)
        #pragma unroll
        for (int j = 0; j < 4; j++)
            #pragma unroll
            for (int q = 0; q < 4; q++) c[i][j][q] = 0.0f;

    for (int k0 = 0; k0 < K; k0 += 32) {
        #pragma unroll
        for (int it = 0; it < 2; it++) {
            int ch = tid + it * 256;
            int r = ch >> 2;
            int kc = (ch & 3) * 8;
            int row = rowBase + r;
            int kk = k0 + kc;
            uint4 vh = make_uint4(0, 0, 0, 0), vl = make_uint4(0, 0, 0, 0);
            if (row < nrows) {
                if (kk < K0) {
                    vh = *(const uint4*)&A0h[(size_t)row * K0 + kk];
                    vl = *(const uint4*)&A0l[(size_t)row * K0 + kk];
                } else {
                    vh = *(const uint4*)&A1h[(size_t)row * K1 + (kk - K0)];
                    vl = *(const uint4*)&A1l[(size_t)row * K1 + (kk - K0)];
                }
            }
            *(uint4*)&As[0][r * PA + kc] = vh;
            *(uint4*)&As[1][r * PA + kc] = vl;
        }
        #pragma unroll
        for (int it = 0; it < 2; it++) {
            int ch = tid + it * 256;
            int n = ch >> 2;
            int kc = (ch & 3) * 8;
            int col = colBase + n;
            int kk = k0 + kc;
            uint4 vh = *(const uint4*)&Bh[(size_t)col * K + kk];
            uint4 vl = *(const uint4*)&Bl[(size_t)col * K + kk];
            *(uint4*)&Bs[0][n * PA + kc] = vh;
            *(uint4*)&Bs[1][n * PA + kc] = vl;
        }
        __syncthreads();

        #pragma unroll
        for (int ks = 0; ks < 2; ks++) {
            int kb = ks * 16;
            unsigned af[4][4], bfh[4][2], bfl[4][2];
            #pragma unroll
            for (int mt = 0; mt < 4; mt++) {
                int rb = wm * 64 + mt * 16;
                af[mt][0] = *(const unsigned*)&As[0][(rb + g) * PA + kb + t2];
                af[mt][1] = *(const unsigned*)&As[0][(rb + g + 8) * PA + kb + t2];
                af[mt][2] = *(const unsigned*)&As[0][(rb + g) * PA + kb + t2 + 8];
                af[mt][3] = *(const unsigned*)&As[0][(rb + g + 8) * PA + kb + t2 + 8];
            }
            #pragma unroll
            for (int nt = 0; nt < 4; nt++) {
                int nb = wn * 32 + nt * 8 + g;
                bfh[nt][0] = *(const unsigned*)&Bs[0][nb * PA + kb + t2];
                bfh[nt][1] = *(const unsigned*)&Bs[0][nb * PA + kb + t2 + 8];
                bfl[nt][0] = *(const unsigned*)&Bs[1][nb * PA + kb + t2];
                bfl[nt][1] = *(const unsigned*)&Bs[1][nb * PA + kb + t2 + 8];
            }
            #pragma unroll
            for (int mt = 0; mt < 4; mt++)
                #pragma unroll
                for (int nt = 0; nt < 4; nt++) {
                    mma16816(c[mt][nt], af[mt], bfh[nt]);
                    mma16816(c[mt][nt], af[mt], bfl[nt]);
                }
            #pragma unroll
            for (int mt = 0; mt < 4; mt++) {
                int rb = wm * 64 + mt * 16;
                af[mt][0] = *(const unsigned*)&As[1][(rb + g) * PA + kb + t2];
                af[mt][1] = *(const unsigned*)&As[1][(rb + g + 8) * PA + kb + t2];
                af[mt][2] = *(const unsigned*)&As[1][(rb + g) * PA + kb + t2 + 8];
                af[mt][3] = *(const unsigned*)&As[1][(rb + g + 8) * PA + kb + t2 + 8];
            }
            #pragma unroll
            for (int mt = 0; mt < 4; mt++)
                #pragma unroll
                for (int nt = 0; nt < 4; nt++)
                    mma16816(c[mt][nt], af[mt], bfh[nt]);
        }
        __syncthreads();
    }

    #pragma unroll
    for (int mt = 0; mt < 4; mt++) {
        #pragma unroll
        for (int nt = 0; nt < 4; nt++) {
            int r0 = rowBase + wm * 64 + mt * 16 + g;
            int cc = colBase + wn * 32 + nt * 8 + t2;
            float bv0 = 0.0f, bv1 = 0.0f;
            if (bias) {
                if (cc >= bias_from)     bv0 = bias[cc - bias_from];
                if (cc + 1 >= bias_from) bv1 = bias[cc + 1 - bias_from];
            }
            #pragma unroll
            for (int half_ : {0, 1}) {
                int row = r0 + half_ * 8;
                if (row >= nrows) continue;
                float v0 = c[mt][nt][half_ * 2 + 0] + bv0;
                float v1 = c[mt][nt][half_ * 2 + 1] + bv1;
                if (relu) { v0 = fmaxf(v0, 0.0f); v1 = fmaxf(v1, 0.0f); }
                if (outHalf) {
                    __half h0, l0, h1, l1;
                    split_f32(v0, h0, l0);
                    split_f32(v1, h1, l1);
                    *(__half2*)&Oh[(size_t)row * ncols + cc] = __halves2half2(h0, h1);
                    *(__half2*)&Ol[(size_t)row * ncols + cc] = __halves2half2(l0, l1);
                } else {
                    *(float2*)&g_pq[(size_t)row * ncols + cc] = make_float2(v0, v1);
                }
            }
        }
    }
}

// ---------------- final: vectorized aggregate p, add q, pool -----------------
// Block = 128 threads = 4 warps per node. Per edge one warp loads the full
// 128-float p row as one float4 warp-LDG (32 lanes x 4 floats); warp w takes
// edges e ≡ w (mod 4). Partials combine in smem; warp0 adds q and does the
// per-feature atomic into the graph sum.
__global__ void __launch_bounds__(128)
k_finalv(const void* __restrict__ batch) {
    int n = blockIdx.x;
    int deg = g_cnt[n];
    int start = g_rowstart[n];
    int tid = threadIdx.x;
    int wid = tid >> 5;
    int lane = tid & 31;

    __shared__ int es[64];
    __shared__ float red[4][128];

    float4 acc = make_float4(0.f, 0.f, 0.f, 0.f);
    for (int b0 = 0; b0 < deg; b0 += 64) {
        int m = min(64, deg - b0);
        __syncthreads();
        if (tid < m) es[tid] = g_inlist[start + b0 + tid];
        __syncthreads();
        for (int e = wid; e < m; e += 4) {
            int r = es[e];
            float4 v = *(const float4*)&g_pq[(size_t)r * 256 + lane * 4];
            acc.x += v.x; acc.y += v.y; acc.z += v.z; acc.w += v.w;
        }
    }

    red[wid][lane * 4 + 0] = acc.x;
    red[wid][lane * 4 + 1] = acc.y;
    red[wid][lane * 4 + 2] = acc.z;
    red[wid][lane * 4 + 3] = acc.w;
    __syncthreads();

    if (wid == 0) {
        float dinv = g_dinv[n];
        int g = ld_idx(batch, n, g_b64);
        float4 qv = *(const float4*)&g_pq[(size_t)n * 256 + 128 + lane * 4];
        float* dst = &g_gsum[g * 128 + lane * 4];
        #pragma unroll
        for (int q = 0; q < 4; q++) {
            int f = lane * 4 + q;
            float s = red[0][f] + red[1][f] + red[2][f] + red[3][f];
            float h2 = s * dinv + ((const float*)&qv)[q];
            atomicAdd(dst + q, h2);
        }
        if (lane == 0) atomicAdd(&g_gcnt[g], 1);
    }
}

// ---------------- layernorm over feature dim per graph ----------------------
__global__ void k_ln(const float* __restrict__ gamma,
                     const float* __restrict__ beta,
                     float* __restrict__ out) {
    int g = blockIdx.x;
    int f = threadIdx.x;
    __shared__ float sh[128];
    float v = g_gsum[g * 128 + f] / fmaxf((float)g_gcnt[g], 1.0f);

    sh[f] = v;
    __syncthreads();
    for (int o = 64; o; o >>= 1) {
        if (f < o) sh[f] += sh[f + o];
        __syncthreads();
    }
    float mean = sh[0] * (1.0f / 128.0f);
    __syncthreads();

    float d = v - mean;
    sh[f] = d * d;
    __syncthreads();
    for (int o = 64; o; o >>= 1) {
        if (f < o) sh[f] += sh[f + o];
        __syncthreads();
    }
    float var = sh[0] * (1.0f / 128.0f);

    out[g * 128 + f] = d * rsqrtf(var + 1e-5f) * gamma[f] + beta[f];
}

// ---------------- launch -----------------------------------------------------
extern "C" void kernel_launch(void* const* d_in, const int* in_sizes, int n_in,
                              void* d_out, int out_size) {
    const float* x     = (const float*)d_in[0];
    const void*  ei    = d_in[1];
    const void*  batch = d_in[2];
    const float* Wl0 = (const float*)d_in[3];
    const float* b0  = (const float*)d_in[4];
    const float* Wr0 = (const float*)d_in[5];
    const float* Wl1 = (const float*)d_in[6];
    const float* b1  = (const float*)d_in[7];
    const float* Wr1 = (const float*)d_in[8];
    const float* Wl2 = (const float*)d_in[9];
    const float* b2  = (const float*)d_in[10];
    const float* Wr2 = (const float*)d_in[11];
    const float* gamma = (const float*)d_in[12];
    const float* beta  = (const float*)d_in[13];
    float* out = (float*)d_out;

    // setup: dtype detect, pointer table, zeroing, weight split (one kernel)
    k_setup<<<768, 256>>>((const int*)ei, (const int*)batch, Wl1, Wr1, Wl2, Wr2);

    // CSR build
    k_count<<<512, 256>>>(ei);
    k_scan1<<<NB_SCAN, SCAN_B>>>();
    k_scan2<<<1, 1>>>();
    k_scan3<<<NB_SCAN, SCAN_B>>>();
    k_scatter<<<512, 256>>>(ei);

    // layer 0 (rank-1) -> h0 planes
    k_layer0<<<(N_NODES * 32 + 255) / 256, 256>>>(x, Wl0, b0, Wr0);

    // layer 1: vectorized gather then h1 = relu([a1|h0] @ [Wl1;Wr1] + b1)
    k_gather1v<<<N_NODES, 128>>>();
    {
        dim3 grid(2, (N_NODES + 127) / 128);
        k_hgemm<<<grid, 256>>>(2, 256, 0, 256, 6, b1, 0, 1, 1, 4, N_NODES, 256);
    }

    // layer 2 fused: g_pq = h1 @ [Wl2 | Wr2], bias b2 on cols >= 128
    {
        dim3 grid(2, (N_NODES + 127) / 128);
        k_hgemm<<<grid, 256>>>(4, 256, -1, 0, 8, b2, 128, 0, 0, 0, N_NODES, 256);
    }

    // aggregate p (one warp-LDG.128 per edge), add q, pool into graph sums
    k_finalv<<<N_NODES, 128>>>(batch);

    // layernorm
    k_ln<<<N_GRAPHS, 128>>>(gamma, beta, out);
}

// round 7
// speedup vs baseline: 1.5367x; 1.5367x over previous
#include <cuda_runtime.h>
#include <cuda_fp16.h>
#include <math.h>

#define N_NODES  50000
#define N_EDGES  800000
#define N_GRAPHS 64
#define SCAN_B   1024
#define NB_SCAN  ((N_NODES + SCAN_B - 1) / SCAN_B)   // 49
#define PA 40                    // smem pitch in halves
#define PLANE (128 * PA)         // halves per plane tile
#define SS (4 * PLANE)           // halves per stage (A hi, A lo, B hi, B lo)
#define SMEM_BYTES (2 * SS * 2)  // 2 stages, 2 bytes/half = 81920

// ---------------- scratch (device globals; no allocation allowed) ----------
__device__ __align__(16) __half g_h0hi[N_NODES * 256];
__device__ __align__(16) __half g_h0lo[N_NODES * 256];
__device__ __align__(16) __half g_a1hi[N_NODES * 256];
__device__ __align__(16) __half g_a1lo[N_NODES * 256];
__device__ __align__(16) __half g_h1hi[N_NODES * 256];
__device__ __align__(16) __half g_h1lo[N_NODES * 256];
__device__ __align__(16) float  g_pq[N_NODES * 256];
__device__ __align__(16) __half g_W1hi[256 * 512];
__device__ __align__(16) __half g_W1lo[256 * 512];
__device__ __align__(16) __half g_W2hi[256 * 256];
__device__ __align__(16) __half g_W2lo[256 * 256];
__device__ float g_dinv[N_NODES];
__device__ int   g_cnt[N_NODES];
__device__ int   g_rowstart[N_NODES];
__device__ int   g_cursor[N_NODES];
__device__ int   g_inlist[N_EDGES];
__device__ float g_gsum[N_GRAPHS * 128];
__device__ int   g_gcnt[N_GRAPHS];
__device__ int   g_bsums[64];

__device__ int     g_ei64;
__device__ int     g_b64;
__device__ __half* g_hp[10];  // 0:h0hi 1:h0lo 2:a1hi 3:a1lo 4:h1hi 5:h1lo 6:W1hi 7:W1lo 8:W2hi 9:W2lo

__device__ __forceinline__ int ld_idx(const void* p, long long i, int is64) {
    return is64 ? (int)((const long long*)p)[i] : ((const int*)p)[i];
}

__device__ __forceinline__ void split_f32(float v, __half& hi, __half& lo) {
    hi = __float2half_rn(v);
    lo = __float2half_rn(v - __half2float(hi));
}

__device__ __forceinline__ unsigned smem_u32(const void* p) {
    return (unsigned)__cvta_generic_to_shared(p);
}

__device__ __forceinline__ void cp16(unsigned dst, const void* src) {
    asm volatile("cp.async.cg.shared.global [%0], [%1], 16;\n" :: "r"(dst), "l"(src));
}

// ---------------- setup: dtype detect + pointers + zero + weight split ------
__global__ void k_setup(const int* ei_w, const int* b_w,
                        const float* __restrict__ Wl1, const float* __restrict__ Wr1,
                        const float* __restrict__ Wl2, const float* __restrict__ Wr2) {
    int i = blockIdx.x * blockDim.x + threadIdx.x;
    if (i == 0) {
        int a = 1;
        for (int k = 0; k < 64; k++) if (ei_w[2 * k + 1] != 0) { a = 0; break; }
        g_ei64 = a;
        a = 1;
        for (int k = 0; k < 64; k++) if (b_w[49001 + 2 * k] != 0) { a = 0; break; }
        g_b64 = a;

        g_hp[0] = g_h0hi; g_hp[1] = g_h0lo;
        g_hp[2] = g_a1hi; g_hp[3] = g_a1lo;
        g_hp[4] = g_h1hi; g_hp[5] = g_h1lo;
        g_hp[6] = g_W1hi; g_hp[7] = g_W1lo;
        g_hp[8] = g_W2hi; g_hp[9] = g_W2lo;
    }
    if (i < 131072) {                       // W1: [n=256][k=512]
        int n = i >> 9, k = i & 511;
        float w = (k < 256) ? Wl1[k * 256 + n] : Wr1[(k - 256) * 256 + n];
        split_f32(w, g_W1hi[i], g_W1lo[i]);
    } else if (i < 196608) {                // W2: [n=256][k=256]
        int j = i - 131072;
        int n = j >> 8, k = j & 255;
        float w = (n < 128) ? Wl2[k * 128 + n] : Wr2[k * 128 + (n - 128)];
        split_f32(w, g_W2hi[j], g_W2lo[j]);
    }
    int stride = gridDim.x * blockDim.x;
    for (int j = i; j < N_NODES; j += stride) g_cnt[j] = 0;
    for (int j = i; j < N_GRAPHS * 128; j += stride) g_gsum[j] = 0.0f;
    for (int j = i; j < N_GRAPHS; j += stride) g_gcnt[j] = 0;
}

// ---------------- CSR build -------------------------------------------------
__global__ void k_count(const void* __restrict__ ei) {
    int is64 = g_ei64;
    int i = blockIdx.x * blockDim.x + threadIdx.x;
    int stride = gridDim.x * blockDim.x;
    for (int e = i; e < N_EDGES; e += stride) {
        int d = ld_idx(ei, (long long)N_EDGES + e, is64);
        atomicAdd(&g_cnt[d], 1);
    }
}

__global__ void k_scan1() {
    __shared__ int s[SCAN_B];
    int i = blockIdx.x * SCAN_B + threadIdx.x;
    int v = (i < N_NODES) ? g_cnt[i] : 0;
    s[threadIdx.x] = v;
    __syncthreads();
    for (int off = 1; off < SCAN_B; off <<= 1) {
        int t = (threadIdx.x >= off) ? s[threadIdx.x - off] : 0;
        __syncthreads();
        s[threadIdx.x] += t;
        __syncthreads();
    }
    if (i < N_NODES) g_rowstart[i] = s[threadIdx.x];
    if (threadIdx.x == SCAN_B - 1) g_bsums[blockIdx.x] = s[SCAN_B - 1];
}

// scan3 also does scan2's job: per-block prefix over the 49 block sums.
__global__ void k_scan3() {
    __shared__ int boff;
    int b = blockIdx.x;
    if (threadIdx.x == 0) {
        int run = 0;
        for (int j = 0; j < b; j++) run += g_bsums[j];
        boff = run;
    }
    __syncthreads();
    int i = b * SCAN_B + threadIdx.x;
    if (i >= N_NODES) return;
    int incl = g_rowstart[i];
    int excl = incl - g_cnt[i] + boff;
    g_rowstart[i] = excl;
    g_cursor[i] = excl;
}

__global__ void k_scatter(const void* __restrict__ ei) {
    int is64 = g_ei64;
    int i = blockIdx.x * blockDim.x + threadIdx.x;
    int stride = gridDim.x * blockDim.x;
    for (int e = i; e < N_EDGES; e += stride) {
        int s = ld_idx(ei, e, is64);
        int d = ld_idx(ei, (long long)N_EDGES + e, is64);
        int pos = atomicAdd(&g_cursor[d], 1);
        g_inlist[pos] = s;
    }
}

// ---------------- layer 0 (rank-1): warp per node ---------------------------
__global__ void k_layer0(const float* __restrict__ x,
                         const float* __restrict__ Wl0,
                         const float* __restrict__ b0,
                         const float* __restrict__ Wr0) {
    int wid = (blockIdx.x * blockDim.x + threadIdx.x) >> 5;
    int lane = threadIdx.x & 31;
    if (wid >= N_NODES) return;
    int deg = g_cnt[wid];
    int start = g_rowstart[wid];
    float s = 0.0f;
    for (int i = lane; i < deg; i += 32) s += x[g_inlist[start + i]];
    #pragma unroll
    for (int o = 16; o; o >>= 1) s += __shfl_xor_sync(0xFFFFFFFFu, s, o);
    float dinv = 1.0f / fmaxf((float)deg, 1.0f);
    if (lane == 0) g_dinv[wid] = dinv;
    float agg = s * dinv;
    float xv = x[wid];
    #pragma unroll
    for (int i = 0; i < 8; i++) {
        int f = i * 32 + lane;
        float v = fmaf(agg, Wl0[f], fmaf(xv, Wr0[f], b0[f]));
        v = fmaxf(v, 0.0f);
        __half hi, lo;
        split_f32(v, hi, lo);
        g_h0hi[wid * 256 + f] = hi;
        g_h0lo[wid * 256 + f] = lo;
    }
}

// ---------------- gather1 (round-4 verbatim): block per node, half2/feat ----
__global__ void k_gather1() {
    int n = blockIdx.x;
    int f2 = threadIdx.x;
    int deg = g_cnt[n];
    int start = g_rowstart[n];
    __shared__ int es[128];
    float ax = 0.0f, ay = 0.0f;
    for (int base = 0; base < deg; base += 128) {
        int m = min(128, deg - base);
        __syncthreads();
        if (f2 < m) es[f2] = g_inlist[start + base + f2];
        __syncthreads();
        for (int e = 0; e < m; e++) {
            int r = es[e];
            __half2 h = *(const __half2*)&g_h0hi[(size_t)r * 256 + 2 * f2];
            __half2 l = *(const __half2*)&g_h0lo[(size_t)r * 256 + 2 * f2];
            float2 fh = __half22float2(h);
            float2 fl = __half22float2(l);
            ax += fh.x + fl.x;
            ay += fh.y + fl.y;
        }
    }
    float dinv = g_dinv[n];
    ax *= dinv; ay *= dinv;
    __half hx, lx, hy, ly;
    split_f32(ax, hx, lx);
    split_f32(ay, hy, ly);
    *(__half2*)&g_a1hi[(size_t)n * 256 + 2 * f2] = __halves2half2(hx, hy);
    *(__half2*)&g_a1lo[(size_t)n * 256 + 2 * f2] = __halves2half2(lx, ly);
}

// ---------------- split-fp16 tensor-core GEMM, cp.async 2-stage pipeline ----
__device__ __forceinline__ void mma16816(float* d, const unsigned* a, const unsigned* b) {
    asm volatile(
        "mma.sync.aligned.m16n8k16.row.col.f32.f16.f16.f32 "
        "{%0,%1,%2,%3}, {%4,%5,%6,%7}, {%8,%9}, {%0,%1,%2,%3};\n"
        : "+f"(d[0]), "+f"(d[1]), "+f"(d[2]), "+f"(d[3])
        : "r"(a[0]), "r"(a[1]), "r"(a[2]), "r"(a[3]), "r"(b[0]), "r"(b[1]));
}

__global__ void __launch_bounds__(256, 2)
k_hgemm(int sA0, int K0, int sA1, int K1, int sB,
        const float* __restrict__ bias, int bias_from, int relu,
        int outHalf, int sOutHi, int nrows, int ncols) {
    const __half* A0h = g_hp[sA0];
    const __half* A0l = g_hp[sA0 + 1];
    const __half* A1h = (sA1 >= 0) ? g_hp[sA1] : (const __half*)0;
    const __half* A1l = (sA1 >= 0) ? g_hp[sA1 + 1] : (const __half*)0;
    const __half* Bh = g_hp[sB];
    const __half* Bl = g_hp[sB + 1];
    __half* Oh = outHalf ? g_hp[sOutHi] : (__half*)0;
    __half* Ol = outHalf ? g_hp[sOutHi + 1] : (__half*)0;

    extern __shared__ __half sm[];   // [2 stages][A hi | A lo | B hi | B lo]

    int tid = threadIdx.x;
    int lane = tid & 31;
    int wid = tid >> 5;
    int wm = wid & 1;
    int wn = wid >> 1;
    int g = lane >> 2;
    int t2 = (lane & 3) * 2;
    int rowBase = blockIdx.y * 128;
    int colBase = blockIdx.x * 128;
    int K = K0 + K1;
    int NIT = K >> 5;

    // per-thread staging coordinates (2 chunks each for A and B)
    int r_[2], kc_[2];
    #pragma unroll
    for (int it = 0; it < 2; it++) {
        int ch = tid + it * 256;
        r_[it] = ch >> 2;
        kc_[it] = (ch & 3) * 8;
    }

    float c[4][4][4];
    #pragma unroll
    for (int i = 0; i < 4; i++)
        #pragma unroll
        for (int j = 0; j < 4; j++)
            #pragma unroll
            for (int q = 0; q < 4; q++) c[i][j][q] = 0.0f;

    auto issue = [&](int iter) {
        int st = iter & 1;
        int k0 = iter << 5;
        __half* base = sm + st * SS;
        #pragma unroll
        for (int it = 0; it < 2; it++) {
            int r = r_[it], kc = kc_[it];
            int row = rowBase + r;
            int kk = k0 + kc;
            unsigned dh = smem_u32(&base[r * PA + kc]);
            unsigned dl = dh + PLANE * 2;
            if (row < nrows) {
                const __half *ph, *pl;
                if (kk < K0) {
                    ph = A0h + (size_t)row * K0 + kk;
                    pl = A0l + (size_t)row * K0 + kk;
                } else {
                    ph = A1h + (size_t)row * K1 + (kk - K0);
                    pl = A1l + (size_t)row * K1 + (kk - K0);
                }
                cp16(dh, ph);
                cp16(dl, pl);
            } else {
                uint4 z = make_uint4(0, 0, 0, 0);
                *(uint4*)&base[r * PA + kc] = z;
                *(uint4*)&base[PLANE + r * PA + kc] = z;
            }
        }
        #pragma unroll
        for (int it = 0; it < 2; it++) {
            int n = r_[it], kc = kc_[it];
            int col = colBase + n;
            int kk = k0 + kc;
            unsigned dh = smem_u32(&base[2 * PLANE + n * PA + kc]);
            cp16(dh, Bh + (size_t)col * K + kk);
            cp16(dh + PLANE * 2, Bl + (size_t)col * K + kk);
        }
        asm volatile("cp.async.commit_group;\n" ::: "memory");
    };

    issue(0);

    for (int iter = 0; iter < NIT; iter++) {
        if (iter + 1 < NIT) {
            issue(iter + 1);
            asm volatile("cp.async.wait_group 1;\n" ::: "memory");
        } else {
            asm volatile("cp.async.wait_group 0;\n" ::: "memory");
        }
        __syncthreads();

        const __half* As0 = sm + (iter & 1) * SS;            // A hi
        const __half* As1 = As0 + PLANE;                     // A lo
        const __half* Bs0 = As0 + 2 * PLANE;                 // B hi
        const __half* Bs1 = As0 + 3 * PLANE;                 // B lo

        #pragma unroll
        for (int ks = 0; ks < 2; ks++) {
            int kb = ks * 16;
            unsigned af[4][4], bfh[4][2], bfl[4][2];
            #pragma unroll
            for (int mt = 0; mt < 4; mt++) {
                int rb = wm * 64 + mt * 16;
                af[mt][0] = *(const unsigned*)&As0[(rb + g) * PA + kb + t2];
                af[mt][1] = *(const unsigned*)&As0[(rb + g + 8) * PA + kb + t2];
                af[mt][2] = *(const unsigned*)&As0[(rb + g) * PA + kb + t2 + 8];
                af[mt][3] = *(const unsigned*)&As0[(rb + g + 8) * PA + kb + t2 + 8];
            }
            #pragma unroll
            for (int nt = 0; nt < 4; nt++) {
                int nb = wn * 32 + nt * 8 + g;
                bfh[nt][0] = *(const unsigned*)&Bs0[nb * PA + kb + t2];
                bfh[nt][1] = *(const unsigned*)&Bs0[nb * PA + kb + t2 + 8];
                bfl[nt][0] = *(const unsigned*)&Bs1[nb * PA + kb + t2];
                bfl[nt][1] = *(const unsigned*)&Bs1[nb * PA + kb + t2 + 8];
            }
            #pragma unroll
            for (int mt = 0; mt < 4; mt++)
                #pragma unroll
                for (int nt = 0; nt < 4; nt++) {
                    mma16816(c[mt][nt], af[mt], bfh[nt]);
                    mma16816(c[mt][nt], af[mt], bfl[nt]);
                }
            #pragma unroll
            for (int mt = 0; mt < 4; mt++) {
                int rb = wm * 64 + mt * 16;
                af[mt][0] = *(const unsigned*)&As1[(rb + g) * PA + kb + t2];
                af[mt][1] = *(const unsigned*)&As1[(rb + g + 8) * PA + kb + t2];
                af[mt][2] = *(const unsigned*)&As1[(rb + g) * PA + kb + t2 + 8];
                af[mt][3] = *(const unsigned*)&As1[(rb + g + 8) * PA + kb + t2 + 8];
            }
            #pragma unroll
            for (int mt = 0; mt < 4; mt++)
                #pragma unroll
                for (int nt = 0; nt < 4; nt++)
                    mma16816(c[mt][nt], af[mt], bfh[nt]);
        }
        __syncthreads();
    }

    #pragma unroll
    for (int mt = 0; mt < 4; mt++) {
        #pragma unroll
        for (int nt = 0; nt < 4; nt++) {
            int r0 = rowBase + wm * 64 + mt * 16 + g;
            int cc = colBase + wn * 32 + nt * 8 + t2;
            float bv0 = 0.0f, bv1 = 0.0f;
            if (bias) {
                if (cc >= bias_from)     bv0 = bias[cc - bias_from];
                if (cc + 1 >= bias_from) bv1 = bias[cc + 1 - bias_from];
            }
            #pragma unroll
            for (int half_ : {0, 1}) {
                int row = r0 + half_ * 8;
                if (row >= nrows) continue;
                float v0 = c[mt][nt][half_ * 2 + 0] + bv0;
                float v1 = c[mt][nt][half_ * 2 + 1] + bv1;
                if (relu) { v0 = fmaxf(v0, 0.0f); v1 = fmaxf(v1, 0.0f); }
                if (outHalf) {
                    __half h0, l0, h1, l1;
                    split_f32(v0, h0, l0);
                    split_f32(v1, h1, l1);
                    *(__half2*)&Oh[(size_t)row * ncols + cc] = __halves2half2(h0, h1);
                    *(__half2*)&Ol[(size_t)row * ncols + cc] = __halves2half2(l0, l1);
                } else {
                    *(float2*)&g_pq[(size_t)row * ncols + cc] = make_float2(v0, v1);
                }
            }
        }
    }
}

// ---------------- final (round-4 verbatim): block per node, 128 threads -----
__global__ void k_final(const void* __restrict__ batch) {
    int n = blockIdx.x;
    int f = threadIdx.x;
    int deg = g_cnt[n];
    int start = g_rowstart[n];
    __shared__ int es[128];
    float acc = 0.0f;
    for (int base = 0; base < deg; base += 128) {
        int m = min(128, deg - base);
        __syncthreads();
        if (f < m) es[f] = g_inlist[start + base + f];
        __syncthreads();
        for (int e = 0; e < m; e++) acc += g_pq[(size_t)es[e] * 256 + f];
    }
    float h2 = acc * g_dinv[n] + g_pq[(size_t)n * 256 + 128 + f];
    int g = ld_idx(batch, n, g_b64);
    atomicAdd(&g_gsum[g * 128 + f], h2);
    if (f == 0) atomicAdd(&g_gcnt[g], 1);
}

// ---------------- layernorm over feature dim per graph ----------------------
__global__ void k_ln(const float* __restrict__ gamma,
                     const float* __restrict__ beta,
                     float* __restrict__ out) {
    int g = blockIdx.x;
    int f = threadIdx.x;
    __shared__ float sh[128];
    float v = g_gsum[g * 128 + f] / fmaxf((float)g_gcnt[g], 1.0f);

    sh[f] = v;
    __syncthreads();
    for (int o = 64; o; o >>= 1) {
        if (f < o) sh[f] += sh[f + o];
        __syncthreads();
    }
    float mean = sh[0] * (1.0f / 128.0f);
    __syncthreads();

    float d = v - mean;
    sh[f] = d * d;
    __syncthreads();
    for (int o = 64; o; o >>= 1) {
        if (f < o) sh[f] += sh[f + o];
        __syncthreads();
    }
    float var = sh[0] * (1.0f / 128.0f);

    out[g * 128 + f] = d * rsqrtf(var + 1e-5f) * gamma[f] + beta[f];
}

// ---------------- launch -----------------------------------------------------
extern "C" void kernel_launch(void* const* d_in, const int* in_sizes, int n_in,
                              void* d_out, int out_size) {
    const float* x     = (const float*)d_in[0];
    const void*  ei    = d_in[1];
    const void*  batch = d_in[2];
    const float* Wl0 = (const float*)d_in[3];
    const float* b0  = (const float*)d_in[4];
    const float* Wr0 = (const float*)d_in[5];
    const float* Wl1 = (const float*)d_in[6];
    const float* b1  = (const float*)d_in[7];
    const float* Wr1 = (const float*)d_in[8];
    const float* Wl2 = (const float*)d_in[9];
    const float* b2  = (const float*)d_in[10];
    const float* Wr2 = (const float*)d_in[11];
    const float* gamma = (const float*)d_in[12];
    const float* beta  = (const float*)d_in[13];
    float* out = (float*)d_out;

    // allow 80KB dynamic smem for the pipelined GEMM (host attr, not captured)
    cudaFuncSetAttribute(k_hgemm, cudaFuncAttributeMaxDynamicSharedMemorySize,
                         SMEM_BYTES);

    // setup: dtype detect, pointer table, zeroing, weight split
    k_setup<<<768, 256>>>((const int*)ei, (const int*)batch, Wl1, Wr1, Wl2, Wr2);

    // CSR build
    k_count<<<512, 256>>>(ei);
    k_scan1<<<NB_SCAN, SCAN_B>>>();
    k_scan3<<<NB_SCAN, SCAN_B>>>();
    k_scatter<<<512, 256>>>(ei);

    // layer 0 (rank-1) -> h0 planes
    k_layer0<<<(N_NODES * 32 + 255) / 256, 256>>>(x, Wl0, b0, Wr0);

    // layer 1: gather then h1 = relu([a1|h0] @ [Wl1;Wr1] + b1)
    k_gather1<<<N_NODES, 128>>>();
    {
        dim3 grid(2, (N_NODES + 127) / 128);
        k_hgemm<<<grid, 256, SMEM_BYTES>>>(2, 256, 0, 256, 6, b1, 0, 1, 1, 4,
                                           N_NODES, 256);
    }

    // layer 2 fused: g_pq = h1 @ [Wl2 | Wr2], bias b2 on cols >= 128
    {
        dim3 grid(2, (N_NODES + 127) / 128);
        k_hgemm<<<grid, 256, SMEM_BYTES>>>(4, 256, -1, 0, 8, b2, 128, 0, 0, 0,
                                           N_NODES, 256);
    }

    // aggregate p, add q, pool into graph sums
    k_final<<<N_NODES, 128>>>(batch);

    // layernorm
    k_ln<<<N_GRAPHS, 128>>>(gamma, beta, out);
}